// round 15
// baseline (speedup 1.0000x reference)
#include <cuda_runtime.h>
#include <cuda_fp16.h>
#include <math.h>
#include <stdint.h>

#define NN 50000
#define EE 800000
#define IN_DIM 128
#define EMB 64
#define HDIM 256
#define RR 12
#define BB 8
#define NGENE 20000
#define NPATH 2000
#define IN1 192
#define NR (NN * RR)
#define NBP ((NR + 1023) / 1024)

#define KT1 (9 * IN1)
#define KT2 (9 * HDIM)
#define KB1 (BB * IN1)
#define KB2 (BB * HDIM)
#define W1P ((KT1 / 2) * 256)
#define W2P ((KT2 / 2) * 256)

// ---------------- static scratch ----------------
__device__ float    g_x0[(size_t)NN * IN1];
__device__ __half   g_x0h[(size_t)NN * IN1];
__device__ float    g_h1[(size_t)NN * HDIM];
__device__ __half   g_h1h[(size_t)NN * HDIM];
__device__ float    g_h2[(size_t)NN * HDIM];
__device__ __half   g_aggBh[(size_t)NN * BB * HDIM];
__device__ uint32_t g_Bp1[W1P];
__device__ uint32_t g_Bp2[W2P];
__device__ int      g_cnt[NR];       // zeroed by k_scanC each run
__device__ int      g_part[NBP];
__device__ int      g_off[NR + 1];
__device__ int      g_wof[NR];
__device__ int      g_esrc[EE];

// ---------------- helpers ----------------
__device__ __forceinline__ uint32_t packh2(float a, float b) {
    half2 h = __floats2half2_rn(a, b);
    return *reinterpret_cast<uint32_t*>(&h);
}
__device__ __forceinline__ void mma16h(float* d, const uint32_t* a, const uint32_t* b) {
    asm volatile(
        "mma.sync.aligned.m16n8k16.row.col.f32.f16.f16.f32 "
        "{%0,%1,%2,%3}, {%4,%5,%6,%7}, {%8,%9}, {%0,%1,%2,%3};"
        : "+f"(d[0]), "+f"(d[1]), "+f"(d[2]), "+f"(d[3])
        : "r"(a[0]), "r"(a[1]), "r"(a[2]), "r"(a[3]), "r"(b[0]), "r"(b[1]));
}
// packed fp32x2 ops (Blackwell PTX; 2 fp32 lanes per instruction)
__device__ __forceinline__ unsigned long long pk2(float a, float b) {
    unsigned long long r;
    asm("mov.b64 %0, {%1, %2};" : "=l"(r) : "f"(a), "f"(b));
    return r;
}
__device__ __forceinline__ void upk2(unsigned long long v, float& a, float& b) {
    asm("mov.b64 {%0, %1}, %2;" : "=f"(a), "=f"(b) : "l"(v));
}
__device__ __forceinline__ unsigned long long add2(unsigned long long a, unsigned long long b) {
    unsigned long long d;
    asm("add.rn.f32x2 %0, %1, %2;" : "=l"(d) : "l"(a), "l"(b));
    return d;
}
__device__ __forceinline__ unsigned long long mul2(unsigned long long a, unsigned long long b) {
    unsigned long long d;
    asm("mul.rn.f32x2 %0, %1, %2;" : "=l"(d) : "l"(a), "l"(b));
    return d;
}
__device__ __forceinline__ unsigned long long fma2(unsigned long long a, unsigned long long b,
                                                   unsigned long long c) {
    unsigned long long d;
    asm("fma.rn.f32x2 %0, %1, %2, %3;" : "=l"(d) : "l"(a), "l"(b), "l"(c));
    return d;
}

// ---------------- 1: build x0 (+fp16) + edge counts + pack B ----------------
__global__ void k_build_count(const float* __restrict__ x,
                              const int* __restrict__ ei, const int* __restrict__ et,
                              const float* __restrict__ b1, const float* __restrict__ r1,
                              const float* __restrict__ b2, const float* __restrict__ r2) {
    int i = blockIdx.x * blockDim.x + threadIdx.x;
    if (i < EE) atomicAdd(&g_cnt[ei[EE + i] * RR + et[i]], 1);
    if (i < W1P + W2P) {
        const float* bas; const float* rt; uint32_t* dst; int w, kbrows;
        if (i < W1P) { w = i; bas = b1; rt = r1; dst = g_Bp1; kbrows = KB1; }
        else         { w = i - W1P; bas = b2; rt = r2; dst = g_Bp2; kbrows = KB2; }
        int kk2 = w >> 8, n = w & 255;
        int k = 2 * kk2;
        float v0, v1;
        if (k < kbrows) { v0 = bas[(size_t)k * 256 + n]; v1 = bas[(size_t)(k + 1) * 256 + n]; }
        else { v0 = rt[(size_t)(k - kbrows) * 256 + n]; v1 = rt[(size_t)(k + 1 - kbrows) * 256 + n]; }
        dst[w] = packh2(v0, v1);
    }
    if (i >= NN * IN1) return;
    int n = i / IN1, c = i - n * IN1;
    float v = (c < IN_DIM) ? x[(size_t)n * IN_DIM + c] : 0.0f;
    g_x0[i] = v;
    g_x0h[i] = __float2half(v);
}

// ---------------- 2a: per-block partial sums ----------------
__global__ void k_scanA() {
    __shared__ int ws[32];
    int b = blockIdx.x, t = threadIdx.x;
    int i = b * 1024 + t;
    int v = (i < NR) ? g_cnt[i] : 0;
#pragma unroll
    for (int o = 16; o; o >>= 1) v += __shfl_down_sync(0xffffffffu, v, o);
    if ((t & 31) == 0) ws[t >> 5] = v;
    __syncthreads();
    if (t < 32) {
        int s = ws[t];
#pragma unroll
        for (int o = 16; o; o >>= 1) s += __shfl_down_sync(0xffffffffu, s, o);
        if (t == 0) g_part[b] = s;
    }
}

// ---------------- 2b: scan partials ----------------
__global__ void k_scanB() {
    __shared__ int bs[1024];
    int t = threadIdx.x;
    int v = (t < NBP) ? g_part[t] : 0;
    bs[t] = v;
    __syncthreads();
    for (int o = 1; o < 1024; o <<= 1) {
        int u = (t >= o) ? bs[t - o] : 0;
        __syncthreads();
        bs[t] += u;
        __syncthreads();
    }
    if (t < NBP) g_part[t] = bs[t] - v;
    if (t == NBP - 1) g_off[NR] = bs[t];
}

// ---------------- 2c: per-element offsets; re-zero g_cnt ----------------
__global__ void k_scanC() {
    __shared__ int bs[1024];
    int b = blockIdx.x, t = threadIdx.x;
    int i = b * 1024 + t;
    int c = (i < NR) ? g_cnt[i] : 0;
    bs[t] = c;
    __syncthreads();
    for (int o = 1; o < 1024; o <<= 1) {
        int u = (t >= o) ? bs[t - o] : 0;
        __syncthreads();
        bs[t] += u;
        __syncthreads();
    }
    if (i < NR) {
        int excl = bs[t] - c + g_part[b];
        g_off[i] = excl;
        g_wof[i] = excl;
        g_cnt[i] = 0;
    }
}

// ---------------- 3: CSR fill + embedding writes ----------------
#define FILL_TOT (EE + (NGENE + NPATH) * EMB)
__global__ void k_fill_embs(const int* __restrict__ ei, const int* __restrict__ et,
                            const int* __restrict__ gidx, const int* __restrict__ pidx,
                            const float* __restrict__ gemb, const float* __restrict__ pemb) {
    int i = blockIdx.x * blockDim.x + threadIdx.x;
    if (i < EE) {
        int flat = ei[EE + i] * RR + et[i];
        int p = atomicAdd(&g_wof[flat], 1);
        g_esrc[p] = ei[i];
    } else if (i < EE + NGENE * EMB) {
        int t = i - EE;
        int g = t / EMB, j = t - g * EMB;
        size_t idx = (size_t)gidx[g] * IN1 + IN_DIM + j;
        float v = g_x0[idx] + gemb[t];
        g_x0[idx] = v;
        g_x0h[idx] = __float2half(v);
    } else if (i < FILL_TOT) {
        int t = i - EE - NGENE * EMB;
        int g = t / EMB, j = t - g * EMB;
        size_t idx = (size_t)pidx[g] * IN1 + IN_DIM + j;
        float v = g_x0[idx] + pemb[t];
        g_x0[idx] = v;
        g_x0h[idx] = __float2half(v);
    }
}

// ---------------- 4/6: gather-aggregate, packed f32x2 math ----------------
template <int K, int LAYER, int NPB>
__global__ void __launch_bounds__((K / 4) * NPB)
k_agg(const float* __restrict__ comp) {
    constexpr int GROUP = K / 4;
    __shared__ unsigned long long sc2[RR * BB];   // comp[r][b] duplicated into both lanes
    const int tid = threadIdx.x;
    for (int i = tid; i < RR * BB; i += GROUP * NPB) {
        float w = comp[i];
        sc2[i] = pk2(w, w);
    }
    __syncthreads();

    const int g    = tid / GROUP;
    const int lane = tid - g * GROUP;
    const int n    = blockIdx.x * NPB + g;
    const int col  = lane * 4;
    const float* __restrict__ xin = (LAYER == 1) ? g_x0 : g_h1;

    unsigned long long accP[BB][2];
#pragma unroll
    for (int b = 0; b < BB; b++) { accP[b][0] = 0ull; accP[b][1] = 0ull; }

    int off0 = g_off[n * RR];
#pragma unroll
    for (int r = 0; r < RR; r++) {
        int off1 = g_off[n * RR + r + 1];
        int c = off1 - off0;
        if (c > 0) {
            unsigned long long s01 = 0ull, s23 = 0ull;
            for (int j = off0; j < off1; j++) {
                int src = __ldg(&g_esrc[j]);
                ulonglong2 v = *reinterpret_cast<const ulonglong2*>(xin + (size_t)src * K + col);
                s01 = add2(s01, v.x);
                s23 = add2(s23, v.y);
            }
            float inv = 1.f / (float)c;
            unsigned long long iv = pk2(inv, inv);
            s01 = mul2(s01, iv);
            s23 = mul2(s23, iv);
#pragma unroll
            for (int b = 0; b < BB; b++) {
                accP[b][0] = fma2(sc2[r * BB + b], s01, accP[b][0]);
                accP[b][1] = fma2(sc2[r * BB + b], s23, accP[b][1]);
            }
        }
        off0 = off1;
    }

    __half* dst = g_aggBh + (size_t)n * (BB * K) + col;
#pragma unroll
    for (int b = 0; b < BB; b++) {
        float a0, a1, a2, a3;
        upk2(accP[b][0], a0, a1);
        upk2(accP[b][1], a2, a3);
        uint2 u = make_uint2(packh2(a0, a1), packh2(a2, a3));
        *reinterpret_cast<uint2*>(dst + b * K) = u;
    }
}

// ---------------- 5/7: GEMM FP16, BK=32, 8 warps, 64x64 warp tile ----------------
#define GEMM_SMEM_BYTES (16128 * 4)

template <int KIN, int LAYER>
__global__ void __launch_bounds__(256, 1)
k_gemm(const float* __restrict__ bias, const float* __restrict__ att) {
    constexpr int KB   = BB * KIN;
    constexpr int KTOT = 9 * KIN;
    constexpr int T    = KTOT / 32;

    extern __shared__ float sm[];
    uint32_t* smw = reinterpret_cast<uint32_t*>(sm);
    float* s_bias = sm + 14592;
    float* s_att  = sm + 14848;
    float* s_sc   = sm + 15104;
    float* s_al   = sm + 15616;

    const int tid  = threadIdx.x;
    const int lane = tid & 31;
    const int wid  = tid >> 5;
    const int wm   = wid >> 2;
    const int wn   = wid & 3;
    const int m0   = blockIdx.x * 128;

    const __half* __restrict__ xinh = (LAYER == 1) ? g_x0h : g_h1h;
    const uint32_t* __restrict__ Bp = (LAYER == 1) ? g_Bp1 : g_Bp2;
    float* hout = (LAYER == 1) ? g_h1 : g_h2;

    s_bias[tid] = bias[tid];
    s_att[tid]  = att[tid];

    float acc[4][8][4];
#pragma unroll
    for (int a = 0; a < 4; a++)
#pragma unroll
        for (int b = 0; b < 8; b++)
#pragma unroll
            for (int c = 0; c < 4; c++) acc[a][b][c] = 0.f;

    uint4 aReg[2];
    uint4 bReg[4];
    const int am  = tid >> 1;
    const int ak8 = (tid & 1) << 3;

    auto gload = [&](int t) {
        int row = m0 + am;
#pragma unroll
        for (int i = 0; i < 2; i++) {
            int kc = t * 32 + i * 16 + ak8;
            if (row < NN) {
                const __half* src = (kc < KB) ? (g_aggBh + (size_t)row * KB + kc)
                                              : (xinh + (size_t)row * KIN + (kc - KB));
                aReg[i] = *reinterpret_cast<const uint4*>(src);
            } else {
                aReg[i] = make_uint4(0u, 0u, 0u, 0u);
            }
        }
#pragma unroll
        for (int i = 0; i < 4; i++) {
            int id = tid + i * 256;
            int kp2 = id >> 6, n4 = (id & 63) << 2;
            bReg[i] = *reinterpret_cast<const uint4*>(Bp + (size_t)(16 * t + kp2) * 256 + n4);
        }
    };
    auto sstore = [&](int t) {
        int s = t & 1;
        uint32_t* Abase = smw + s * 3072;
#pragma unroll
        for (int i = 0; i < 2; i++)
            *reinterpret_cast<uint4*>(Abase + i * 1536 + am * 12 + (ak8 >> 1)) = aReg[i];
        uint32_t* Bbase = smw + 6144 + s * 4224;
#pragma unroll
        for (int i = 0; i < 4; i++) {
            int id = tid + i * 256;
            int kp2 = id >> 6, n4 = (id & 63) << 2;
            *reinterpret_cast<uint4*>(Bbase + (kp2 >> 3) * 2112 + (kp2 & 7) * 264 + n4) = bReg[i];
        }
    };

    gload(0);
    sstore(0);
    if (T > 1) gload(1);
    __syncthreads();

    for (int t = 0; t < T; t++) {
        const uint32_t* Abase = smw + (t & 1) * 3072;
        const uint32_t* Bbase = smw + 6144 + (t & 1) * 4224;
        const int c = lane & 3;
#pragma unroll
        for (int ss = 0; ss < 2; ss++) {
            const uint32_t* Ah = Abase + ss * 1536;
            const uint32_t* Bh = Bbase + ss * 2112;
            uint32_t ah[4][4];
#pragma unroll
            for (int mi = 0; mi < 4; mi++) {
                int r0 = wm * 64 + mi * 16 + (lane >> 2);
                int i0 = r0 * 12 + c;
                int i1 = (r0 + 8) * 12 + c;
                ah[mi][0] = Ah[i0];     ah[mi][1] = Ah[i1];
                ah[mi][2] = Ah[i0 + 4]; ah[mi][3] = Ah[i1 + 4];
            }
            uint32_t bh[8][2];
#pragma unroll
            for (int ni = 0; ni < 8; ni++) {
                int n = wn * 64 + ni * 8 + (lane >> 2);
                bh[ni][0] = Bh[c * 264 + n];
                bh[ni][1] = Bh[(c + 4) * 264 + n];
            }
#pragma unroll
            for (int ni = 0; ni < 8; ni++)
#pragma unroll
                for (int mi = 0; mi < 4; mi++) mma16h(acc[mi][ni], ah[mi], bh[ni]);
        }
        if (t + 1 < T) sstore(t + 1);
        if (t + 2 < T) gload(t + 2);
        __syncthreads();
    }

    // ---- bias + head scores ----
    float scv[8];
#pragma unroll
    for (int i = 0; i < 8; ++i) scv[i] = 0.f;
#pragma unroll
    for (int mi = 0; mi < 4; ++mi)
#pragma unroll
        for (int ni = 0; ni < 8; ++ni) {
            int colb = wn * 64 + ni * 8 + (lane & 3) * 2;
#pragma unroll
            for (int r = 0; r < 4; ++r) {
                int col = colb + (r & 1);
                acc[mi][ni][r] += s_bias[col];
                scv[mi * 2 + (r >> 1)] = fmaf(acc[mi][ni][r], s_att[col], scv[mi * 2 + (r >> 1)]);
            }
        }
#pragma unroll
    for (int i = 0; i < 8; ++i) {
        scv[i] += __shfl_xor_sync(0xffffffffu, scv[i], 1);
        scv[i] += __shfl_xor_sync(0xffffffffu, scv[i], 2);
    }
    if ((lane & 3) == 0) {
#pragma unroll
        for (int mi = 0; mi < 4; ++mi) {
            int r0 = wm * 64 + mi * 16 + (lane >> 2);
            s_sc[r0 * 4 + wn]       = scv[mi * 2];
            s_sc[(r0 + 8) * 4 + wn] = scv[mi * 2 + 1];
        }
    }
    __syncthreads();
    if (tid < 128) {
        float v0 = s_sc[tid * 4], v1 = s_sc[tid * 4 + 1];
        float v2 = s_sc[tid * 4 + 2], v3 = s_sc[tid * 4 + 3];
        float mx = fmaxf(fmaxf(v0, v1), fmaxf(v2, v3));
        float e0 = expf(v0 - mx), e1 = expf(v1 - mx), e2 = expf(v2 - mx), e3 = expf(v3 - mx);
        float inv = 1.f / (e0 + e1 + e2 + e3);
        s_al[tid * 4]     = e0 * inv;
        s_al[tid * 4 + 1] = e1 * inv;
        s_al[tid * 4 + 2] = e2 * inv;
        s_al[tid * 4 + 3] = e3 * inv;
    }
    __syncthreads();

    // ---- scaled store ----
#pragma unroll
    for (int mi = 0; mi < 4; ++mi) {
        int lr0 = wm * 64 + mi * 16 + (lane >> 2);
        int rowA = m0 + lr0, rowB = rowA + 8;
        float aA = s_al[lr0 * 4 + wn];
        float aB = s_al[(lr0 + 8) * 4 + wn];
#pragma unroll
        for (int ni = 0; ni < 8; ++ni) {
            int col = wn * 64 + ni * 8 + (lane & 3) * 2;
            if (rowA < NN) {
                float ox = acc[mi][ni][0] * aA, oy = acc[mi][ni][1] * aA;
                *reinterpret_cast<float2*>(&hout[(size_t)rowA * HDIM + col]) = make_float2(ox, oy);
                if (LAYER == 1)
                    *reinterpret_cast<uint32_t*>(g_h1h + (size_t)rowA * HDIM + col) = packh2(ox, oy);
            }
            if (rowB < NN) {
                float ox = acc[mi][ni][2] * aB, oy = acc[mi][ni][3] * aB;
                *reinterpret_cast<float2*>(&hout[(size_t)rowB * HDIM + col]) = make_float2(ox, oy);
                if (LAYER == 1)
                    *reinterpret_cast<uint32_t*>(g_h1h + (size_t)rowB * HDIM + col) = packh2(ox, oy);
            }
        }
    }
}

// ---------------- 8: final prediction ----------------
__global__ void k_pred(const float* __restrict__ pw, const float* __restrict__ pb,
                       float* __restrict__ out) {
    __shared__ float wt[12 * HDIM];
    int tid = threadIdx.x;
    for (int i = tid; i < HDIM * 12; i += blockDim.x) {
        int c = i / 12, j = i - c * 12;
        wt[j * HDIM + c] = pw[i];
    }
    __syncthreads();
    int warp = tid >> 5, lane = tid & 31;
    int n = blockIdx.x * 8 + warp;
    if (n >= NN) return;
    float acc[12];
#pragma unroll
    for (int j = 0; j < 12; j++) acc[j] = 0.f;
#pragma unroll
    for (int c0 = 0; c0 < 8; c0++) {
        int c = c0 * 32 + lane;
        float v = g_h2[(size_t)n * HDIM + c];
#pragma unroll
        for (int j = 0; j < 12; j++) acc[j] = fmaf(v, wt[j * HDIM + c], acc[j]);
    }
#pragma unroll
    for (int j = 0; j < 12; j++) {
#pragma unroll
        for (int off = 16; off; off >>= 1)
            acc[j] += __shfl_xor_sync(0xffffffffu, acc[j], off);
    }
    if (lane == 0) {
#pragma unroll
        for (int j = 0; j < 12; j++) out[(size_t)n * 12 + j] = acc[j] + pb[j];
    }
}

// ---------------- launch ----------------
extern "C" void kernel_launch(void* const* d_in, const int* in_sizes, int n_in,
                              void* d_out, int out_size) {
    const float* x      = (const float*)d_in[0];
    const int*   ei     = (const int*)d_in[1];
    const int*   et     = (const int*)d_in[2];
    const int*   gidx   = (const int*)d_in[3];
    const int*   pidx   = (const int*)d_in[4];
    const float* gemb   = (const float*)d_in[5];
    const float* pemb   = (const float*)d_in[6];
    const float* comp1  = (const float*)d_in[7];
    const float* basis1 = (const float*)d_in[8];
    const float* root1  = (const float*)d_in[9];
    const float* bias1  = (const float*)d_in[10];
    const float* att1   = (const float*)d_in[11];
    const float* comp2  = (const float*)d_in[12];
    const float* basis2 = (const float*)d_in[13];
    const float* root2  = (const float*)d_in[14];
    const float* bias2  = (const float*)d_in[15];
    const float* att2   = (const float*)d_in[16];
    const float* predw  = (const float*)d_in[17];
    const float* predb  = (const float*)d_in[18];
    float* out = (float*)d_out;

    const int TPB = 256;

    cudaFuncSetAttribute(k_gemm<IN1, 1>,  cudaFuncAttributeMaxDynamicSharedMemorySize, GEMM_SMEM_BYTES);
    cudaFuncSetAttribute(k_gemm<HDIM, 2>, cudaFuncAttributeMaxDynamicSharedMemorySize, GEMM_SMEM_BYTES);

    // 1: x0 (+fp16) + counts + pack B
    k_build_count<<<(NN * IN1 + TPB - 1) / TPB, TPB>>>(x, ei, et, basis1, root1, basis2, root2);
    // 2: parallel scan
    k_scanA<<<NBP, 1024>>>();
    k_scanB<<<1, 1024>>>();
    k_scanC<<<NBP, 1024>>>();
    // 3: CSR fill + embeddings
    k_fill_embs<<<(FILL_TOT + TPB - 1) / TPB, TPB>>>(ei, et, gidx, pidx, gemb, pemb);
    // 4: aggregate layer 1
    k_agg<IN1, 1, 4><<<NN / 4, (IN1 / 4) * 4>>>(comp1);
    // 5: GEMM layer 1
    k_gemm<IN1, 1><<<(NN + 127) / 128, 256, GEMM_SMEM_BYTES>>>(bias1, att1);
    // 6: aggregate layer 2
    k_agg<HDIM, 2, 4><<<NN / 4, (HDIM / 4) * 4>>>(comp2);
    // 7: GEMM layer 2
    k_gemm<HDIM, 2><<<(NN + 127) / 128, 256, GEMM_SMEM_BYTES>>>(bias2, att2);
    // 8: prediction head
    k_pred<<<(NN + 7) / 8, TPB>>>(predw, predb, out);
}

// round 16
// speedup vs baseline: 1.1409x; 1.1409x over previous
#include <cuda_runtime.h>
#include <cuda_fp16.h>
#include <math.h>
#include <stdint.h>

#define NN 50000
#define EE 800000
#define IN_DIM 128
#define EMB 64
#define HDIM 256
#define RR 12
#define BB 8
#define NGENE 20000
#define NPATH 2000
#define IN1 192
#define NR (NN * RR)
#define NBP ((NR + 1023) / 1024)

#define KT1 (9 * IN1)
#define KT2 (9 * HDIM)
#define KB1 (BB * IN1)
#define KB2 (BB * HDIM)
#define W1P ((KT1 / 2) * 256)
#define W2P ((KT2 / 2) * 256)

// ---------------- static scratch ----------------
__device__ float    g_x0[(size_t)NN * IN1];
__device__ __half   g_x0h[(size_t)NN * IN1];
__device__ float    g_h1[(size_t)NN * HDIM];
__device__ __half   g_h1h[(size_t)NN * HDIM];
__device__ __half   g_aggBh[(size_t)NN * BB * HDIM];
__device__ uint32_t g_Bp1[W1P];
__device__ uint32_t g_Bp2[W2P];
__device__ int      g_cnt[NR];       // zeroed by k_scanC each run
__device__ int      g_part[NBP];
__device__ int      g_off[NR + 1];
__device__ int      g_wof[NR];
__device__ int      g_esrc[EE];

// ---------------- helpers ----------------
__device__ __forceinline__ uint32_t packh2(float a, float b) {
    half2 h = __floats2half2_rn(a, b);
    return *reinterpret_cast<uint32_t*>(&h);
}
__device__ __forceinline__ void mma16h(float* d, const uint32_t* a, const uint32_t* b) {
    asm volatile(
        "mma.sync.aligned.m16n8k16.row.col.f32.f16.f16.f32 "
        "{%0,%1,%2,%3}, {%4,%5,%6,%7}, {%8,%9}, {%0,%1,%2,%3};"
        : "+f"(d[0]), "+f"(d[1]), "+f"(d[2]), "+f"(d[3])
        : "r"(a[0]), "r"(a[1]), "r"(a[2]), "r"(a[3]), "r"(b[0]), "r"(b[1]));
}

// ---------------- 1: build x0 (+fp16) + edge counts + pack B ----------------
__global__ void k_build_count(const float* __restrict__ x,
                              const int* __restrict__ ei, const int* __restrict__ et,
                              const float* __restrict__ b1, const float* __restrict__ r1,
                              const float* __restrict__ b2, const float* __restrict__ r2) {
    int i = blockIdx.x * blockDim.x + threadIdx.x;
    if (i < EE) atomicAdd(&g_cnt[ei[EE + i] * RR + et[i]], 1);
    if (i < W1P + W2P) {
        const float* bas; const float* rt; uint32_t* dst; int w, kbrows;
        if (i < W1P) { w = i; bas = b1; rt = r1; dst = g_Bp1; kbrows = KB1; }
        else         { w = i - W1P; bas = b2; rt = r2; dst = g_Bp2; kbrows = KB2; }
        int kk2 = w >> 8, n = w & 255;
        int k = 2 * kk2;
        float v0, v1;
        if (k < kbrows) { v0 = bas[(size_t)k * 256 + n]; v1 = bas[(size_t)(k + 1) * 256 + n]; }
        else { v0 = rt[(size_t)(k - kbrows) * 256 + n]; v1 = rt[(size_t)(k + 1 - kbrows) * 256 + n]; }
        dst[w] = packh2(v0, v1);
    }
    if (i >= NN * IN1) return;
    int n = i / IN1, c = i - n * IN1;
    float v = (c < IN_DIM) ? x[(size_t)n * IN_DIM + c] : 0.0f;
    g_x0[i] = v;
    g_x0h[i] = __float2half(v);
}

// ---------------- 2a: per-block partial sums ----------------
__global__ void k_scanA() {
    __shared__ int ws[32];
    int b = blockIdx.x, t = threadIdx.x;
    int i = b * 1024 + t;
    int v = (i < NR) ? g_cnt[i] : 0;
#pragma unroll
    for (int o = 16; o; o >>= 1) v += __shfl_down_sync(0xffffffffu, v, o);
    if ((t & 31) == 0) ws[t >> 5] = v;
    __syncthreads();
    if (t < 32) {
        int s = ws[t];
#pragma unroll
        for (int o = 16; o; o >>= 1) s += __shfl_down_sync(0xffffffffu, s, o);
        if (t == 0) g_part[b] = s;
    }
}

// ---------------- 2b: scan partials ----------------
__global__ void k_scanB() {
    __shared__ int bs[1024];
    int t = threadIdx.x;
    int v = (t < NBP) ? g_part[t] : 0;
    bs[t] = v;
    __syncthreads();
    for (int o = 1; o < 1024; o <<= 1) {
        int u = (t >= o) ? bs[t - o] : 0;
        __syncthreads();
        bs[t] += u;
        __syncthreads();
    }
    if (t < NBP) g_part[t] = bs[t] - v;
    if (t == NBP - 1) g_off[NR] = bs[t];
}

// ---------------- 2c: per-element offsets; re-zero g_cnt ----------------
__global__ void k_scanC() {
    __shared__ int bs[1024];
    int b = blockIdx.x, t = threadIdx.x;
    int i = b * 1024 + t;
    int c = (i < NR) ? g_cnt[i] : 0;
    bs[t] = c;
    __syncthreads();
    for (int o = 1; o < 1024; o <<= 1) {
        int u = (t >= o) ? bs[t - o] : 0;
        __syncthreads();
        bs[t] += u;
        __syncthreads();
    }
    if (i < NR) {
        int excl = bs[t] - c + g_part[b];
        g_off[i] = excl;
        g_wof[i] = excl;
        g_cnt[i] = 0;
    }
}

// ---------------- 3: CSR fill + embedding writes ----------------
#define FILL_TOT (EE + (NGENE + NPATH) * EMB)
__global__ void k_fill_embs(const int* __restrict__ ei, const int* __restrict__ et,
                            const int* __restrict__ gidx, const int* __restrict__ pidx,
                            const float* __restrict__ gemb, const float* __restrict__ pemb) {
    int i = blockIdx.x * blockDim.x + threadIdx.x;
    if (i < EE) {
        int flat = ei[EE + i] * RR + et[i];
        int p = atomicAdd(&g_wof[flat], 1);
        g_esrc[p] = ei[i];
    } else if (i < EE + NGENE * EMB) {
        int t = i - EE;
        int g = t / EMB, j = t - g * EMB;
        size_t idx = (size_t)gidx[g] * IN1 + IN_DIM + j;
        float v = g_x0[idx] + gemb[t];
        g_x0[idx] = v;
        g_x0h[idx] = __float2half(v);
    } else if (i < FILL_TOT) {
        int t = i - EE - NGENE * EMB;
        int g = t / EMB, j = t - g * EMB;
        size_t idx = (size_t)pidx[g] * IN1 + IN_DIM + j;
        float v = g_x0[idx] + pemb[t];
        g_x0[idx] = v;
        g_x0h[idx] = __float2half(v);
    }
}

// ---------------- 4/6: gather-aggregate (fp32 in, fp16 out) ----------------
template <int K, int LAYER, int NPB>
__global__ void __launch_bounds__((K / 4) * NPB)
k_agg(const float* __restrict__ comp) {
    constexpr int GROUP = K / 4;
    __shared__ float sc[RR * BB];
    const int tid = threadIdx.x;
    for (int i = tid; i < RR * BB; i += GROUP * NPB) sc[i] = comp[i];
    __syncthreads();

    const int g    = tid / GROUP;
    const int lane = tid - g * GROUP;
    const int n    = blockIdx.x * NPB + g;
    const int col  = lane * 4;
    const float* __restrict__ xin = (LAYER == 1) ? g_x0 : g_h1;

    float4 accB[BB];
#pragma unroll
    for (int b = 0; b < BB; b++) accB[b] = make_float4(0.f, 0.f, 0.f, 0.f);

    int off0 = g_off[n * RR];
#pragma unroll
    for (int r = 0; r < RR; r++) {
        int off1 = g_off[n * RR + r + 1];
        int c = off1 - off0;
        if (c > 0) {
            float4 s = make_float4(0.f, 0.f, 0.f, 0.f);
            for (int j = off0; j < off1; j++) {
                int src = __ldg(&g_esrc[j]);
                float4 v = *reinterpret_cast<const float4*>(xin + (size_t)src * K + col);
                s.x += v.x; s.y += v.y; s.z += v.z; s.w += v.w;
            }
            float inv = 1.f / (float)c;
#pragma unroll
            for (int b = 0; b < BB; b++) {
                float w = sc[r * BB + b] * inv;
                accB[b].x = fmaf(w, s.x, accB[b].x);
                accB[b].y = fmaf(w, s.y, accB[b].y);
                accB[b].z = fmaf(w, s.z, accB[b].z);
                accB[b].w = fmaf(w, s.w, accB[b].w);
            }
        }
        off0 = off1;
    }

    __half* dst = g_aggBh + (size_t)n * (BB * K) + col;
#pragma unroll
    for (int b = 0; b < BB; b++) {
        uint2 u = make_uint2(packh2(accB[b].x, accB[b].y), packh2(accB[b].z, accB[b].w));
        *reinterpret_cast<uint2*>(dst + b * K) = u;
    }
}

// ---------------- 5/7: GEMM FP16, BK=32; LAYER2 fuses the prediction head ----------------
// words/stage: A 2x[128][12]=3072 | B 2x[8][264]=4224; 2 stages: A 6144, B 8448 @6144.
// bias@14592 att@14848 sc@15104(512) al@15616(512) -> 16128 words = 64512 B
// post-mainloop (LAYER2): tile region reused: wt[12*256]@0, sp[4][128][12]@3072
#define GEMM_SMEM_BYTES (16128 * 4)

template <int KIN, int LAYER>
__global__ void __launch_bounds__(256, 1)
k_gemm(const float* __restrict__ bias, const float* __restrict__ att,
       const float* __restrict__ pw, const float* __restrict__ pb,
       float* __restrict__ out) {
    constexpr int KB   = BB * KIN;
    constexpr int KTOT = 9 * KIN;
    constexpr int T    = KTOT / 32;

    extern __shared__ float sm[];
    uint32_t* smw = reinterpret_cast<uint32_t*>(sm);
    float* s_bias = sm + 14592;
    float* s_att  = sm + 14848;
    float* s_sc   = sm + 15104;
    float* s_al   = sm + 15616;

    const int tid  = threadIdx.x;
    const int lane = tid & 31;
    const int wid  = tid >> 5;
    const int wm   = wid >> 2;
    const int wn   = wid & 3;
    const int m0   = blockIdx.x * 128;

    const __half* __restrict__ xinh = (LAYER == 1) ? g_x0h : g_h1h;
    const uint32_t* __restrict__ Bp = (LAYER == 1) ? g_Bp1 : g_Bp2;

    s_bias[tid] = bias[tid];
    s_att[tid]  = att[tid];

    float acc[4][8][4];
#pragma unroll
    for (int a = 0; a < 4; a++)
#pragma unroll
        for (int b = 0; b < 8; b++)
#pragma unroll
            for (int c = 0; c < 4; c++) acc[a][b][c] = 0.f;

    uint4 aReg[2];
    uint4 bReg[4];
    const int am  = tid >> 1;
    const int ak8 = (tid & 1) << 3;

    auto gload = [&](int t) {
        int row = m0 + am;
#pragma unroll
        for (int i = 0; i < 2; i++) {
            int kc = t * 32 + i * 16 + ak8;
            if (row < NN) {
                const __half* src = (kc < KB) ? (g_aggBh + (size_t)row * KB + kc)
                                              : (xinh + (size_t)row * KIN + (kc - KB));
                aReg[i] = *reinterpret_cast<const uint4*>(src);
            } else {
                aReg[i] = make_uint4(0u, 0u, 0u, 0u);
            }
        }
#pragma unroll
        for (int i = 0; i < 4; i++) {
            int id = tid + i * 256;
            int kp2 = id >> 6, n4 = (id & 63) << 2;
            bReg[i] = *reinterpret_cast<const uint4*>(Bp + (size_t)(16 * t + kp2) * 256 + n4);
        }
    };
    auto sstore = [&](int t) {
        int s = t & 1;
        uint32_t* Abase = smw + s * 3072;
#pragma unroll
        for (int i = 0; i < 2; i++)
            *reinterpret_cast<uint4*>(Abase + i * 1536 + am * 12 + (ak8 >> 1)) = aReg[i];
        uint32_t* Bbase = smw + 6144 + s * 4224;
#pragma unroll
        for (int i = 0; i < 4; i++) {
            int id = tid + i * 256;
            int kp2 = id >> 6, n4 = (id & 63) << 2;
            *reinterpret_cast<uint4*>(Bbase + (kp2 >> 3) * 2112 + (kp2 & 7) * 264 + n4) = bReg[i];
        }
    };

    gload(0);
    sstore(0);
    if (T > 1) gload(1);
    __syncthreads();

    for (int t = 0; t < T; t++) {
        const uint32_t* Abase = smw + (t & 1) * 3072;
        const uint32_t* Bbase = smw + 6144 + (t & 1) * 4224;
        const int c = lane & 3;
#pragma unroll
        for (int ss = 0; ss < 2; ss++) {
            const uint32_t* Ah = Abase + ss * 1536;
            const uint32_t* Bh = Bbase + ss * 2112;
            uint32_t ah[4][4];
#pragma unroll
            for (int mi = 0; mi < 4; mi++) {
                int r0 = wm * 64 + mi * 16 + (lane >> 2);
                int i0 = r0 * 12 + c;
                int i1 = (r0 + 8) * 12 + c;
                ah[mi][0] = Ah[i0];     ah[mi][1] = Ah[i1];
                ah[mi][2] = Ah[i0 + 4]; ah[mi][3] = Ah[i1 + 4];
            }
            uint32_t bh[8][2];
#pragma unroll
            for (int ni = 0; ni < 8; ni++) {
                int n = wn * 64 + ni * 8 + (lane >> 2);
                bh[ni][0] = Bh[c * 264 + n];
                bh[ni][1] = Bh[(c + 4) * 264 + n];
            }
#pragma unroll
            for (int ni = 0; ni < 8; ni++)
#pragma unroll
                for (int mi = 0; mi < 4; mi++) mma16h(acc[mi][ni], ah[mi], bh[ni]);
        }
        if (t + 1 < T) sstore(t + 1);
        if (t + 2 < T) gload(t + 2);
        __syncthreads();
    }

    // ---- bias + head scores (warp tile == one full head) ----
    float scv[8];
#pragma unroll
    for (int i = 0; i < 8; ++i) scv[i] = 0.f;
#pragma unroll
    for (int mi = 0; mi < 4; ++mi)
#pragma unroll
        for (int ni = 0; ni < 8; ++ni) {
            int colb = wn * 64 + ni * 8 + (lane & 3) * 2;
#pragma unroll
            for (int r = 0; r < 4; ++r) {
                int col = colb + (r & 1);
                acc[mi][ni][r] += s_bias[col];
                scv[mi * 2 + (r >> 1)] = fmaf(acc[mi][ni][r], s_att[col], scv[mi * 2 + (r >> 1)]);
            }
        }
#pragma unroll
    for (int i = 0; i < 8; ++i) {
        scv[i] += __shfl_xor_sync(0xffffffffu, scv[i], 1);
        scv[i] += __shfl_xor_sync(0xffffffffu, scv[i], 2);
    }
    if ((lane & 3) == 0) {
#pragma unroll
        for (int mi = 0; mi < 4; ++mi) {
            int r0 = wm * 64 + mi * 16 + (lane >> 2);
            s_sc[r0 * 4 + wn]       = scv[mi * 2];
            s_sc[(r0 + 8) * 4 + wn] = scv[mi * 2 + 1];
        }
    }
    __syncthreads();
    if (tid < 128) {
        float v0 = s_sc[tid * 4], v1 = s_sc[tid * 4 + 1];
        float v2 = s_sc[tid * 4 + 2], v3 = s_sc[tid * 4 + 3];
        float mx = fmaxf(fmaxf(v0, v1), fmaxf(v2, v3));
        float e0 = expf(v0 - mx), e1 = expf(v1 - mx), e2 = expf(v2 - mx), e3 = expf(v3 - mx);
        float inv = 1.f / (e0 + e1 + e2 + e3);
        s_al[tid * 4]     = e0 * inv;
        s_al[tid * 4 + 1] = e1 * inv;
        s_al[tid * 4 + 2] = e2 * inv;
        s_al[tid * 4 + 3] = e3 * inv;
    }
    __syncthreads();

    if (LAYER == 1) {
        // ---- scaled store: fp32 h1 + fp16 copy ----
#pragma unroll
        for (int mi = 0; mi < 4; ++mi) {
            int lr0 = wm * 64 + mi * 16 + (lane >> 2);
            int rowA = m0 + lr0, rowB = rowA + 8;
            float aA = s_al[lr0 * 4 + wn];
            float aB = s_al[(lr0 + 8) * 4 + wn];
#pragma unroll
            for (int ni = 0; ni < 8; ++ni) {
                int col = wn * 64 + ni * 8 + (lane & 3) * 2;
                if (rowA < NN) {
                    float ox = acc[mi][ni][0] * aA, oy = acc[mi][ni][1] * aA;
                    *reinterpret_cast<float2*>(&g_h1[(size_t)rowA * HDIM + col]) = make_float2(ox, oy);
                    *reinterpret_cast<uint32_t*>(g_h1h + (size_t)rowA * HDIM + col) = packh2(ox, oy);
                }
                if (rowB < NN) {
                    float ox = acc[mi][ni][2] * aB, oy = acc[mi][ni][3] * aB;
                    *reinterpret_cast<float2*>(&g_h1[(size_t)rowB * HDIM + col]) = make_float2(ox, oy);
                    *reinterpret_cast<uint32_t*>(g_h1h + (size_t)rowB * HDIM + col) = packh2(ox, oy);
                }
            }
        }
    } else {
        // ---- fused prediction head: out[n,:] = (alpha*h2)[n,:] @ pred_w + pred_b ----
        // tile smem is dead; reuse: wt[12*256] @ sm+0, sp[4][128][12] @ sm+3072
        float* wt = sm;
        float* sp = sm + 3072;
        for (int i = tid; i < 12 * 256; i += 256)
            wt[i] = pw[(size_t)(i & 255) * 12 + (i >> 8)];
        __syncthreads();
#pragma unroll
        for (int mi = 0; mi < 4; ++mi) {
            int lr0 = wm * 64 + mi * 16 + (lane >> 2);
            float aA = s_al[lr0 * 4 + wn];
            float aB = s_al[(lr0 + 8) * 4 + wn];
            float pA[12], pB[12];
#pragma unroll
            for (int j = 0; j < 12; j++) { pA[j] = 0.f; pB[j] = 0.f; }
#pragma unroll
            for (int ni = 0; ni < 8; ++ni) {
                int colb = wn * 64 + ni * 8 + (lane & 3) * 2;
                float vA0 = acc[mi][ni][0] * aA, vA1 = acc[mi][ni][1] * aA;
                float vB0 = acc[mi][ni][2] * aB, vB1 = acc[mi][ni][3] * aB;
#pragma unroll
                for (int j = 0; j < 12; j++) {
                    float w0 = wt[j * 256 + colb], w1 = wt[j * 256 + colb + 1];
                    pA[j] = fmaf(vA0, w0, fmaf(vA1, w1, pA[j]));
                    pB[j] = fmaf(vB0, w0, fmaf(vB1, w1, pB[j]));
                }
            }
#pragma unroll
            for (int j = 0; j < 12; j++) {
                pA[j] += __shfl_xor_sync(0xffffffffu, pA[j], 1);
                pA[j] += __shfl_xor_sync(0xffffffffu, pA[j], 2);
                pB[j] += __shfl_xor_sync(0xffffffffu, pB[j], 1);
                pB[j] += __shfl_xor_sync(0xffffffffu, pB[j], 2);
            }
            if ((lane & 3) == 0) {
#pragma unroll
                for (int j = 0; j < 12; j++) {
                    sp[((size_t)wn * 128 + lr0) * 12 + j]       = pA[j];
                    sp[((size_t)wn * 128 + lr0 + 8) * 12 + j]   = pB[j];
                }
            }
        }
        __syncthreads();
        for (int i = tid; i < 128 * 12; i += 256) {
            int row = i / 12, j = i - row * 12;
            int n = m0 + row;
            if (n < NN) {
                float s = sp[row * 12 + j] + sp[(128 + row) * 12 + j]
                        + sp[(256 + row) * 12 + j] + sp[(384 + row) * 12 + j] + pb[j];
                out[(size_t)n * 12 + j] = s;
            }
        }
    }
}

// ---------------- launch ----------------
extern "C" void kernel_launch(void* const* d_in, const int* in_sizes, int n_in,
                              void* d_out, int out_size) {
    const float* x      = (const float*)d_in[0];
    const int*   ei     = (const int*)d_in[1];
    const int*   et     = (const int*)d_in[2];
    const int*   gidx   = (const int*)d_in[3];
    const int*   pidx   = (const int*)d_in[4];
    const float* gemb   = (const float*)d_in[5];
    const float* pemb   = (const float*)d_in[6];
    const float* comp1  = (const float*)d_in[7];
    const float* basis1 = (const float*)d_in[8];
    const float* root1  = (const float*)d_in[9];
    const float* bias1  = (const float*)d_in[10];
    const float* att1   = (const float*)d_in[11];
    const float* comp2  = (const float*)d_in[12];
    const float* basis2 = (const float*)d_in[13];
    const float* root2  = (const float*)d_in[14];
    const float* bias2  = (const float*)d_in[15];
    const float* att2   = (const float*)d_in[16];
    const float* predw  = (const float*)d_in[17];
    const float* predb  = (const float*)d_in[18];
    float* out = (float*)d_out;

    const int TPB = 256;

    cudaFuncSetAttribute(k_gemm<IN1, 1>,  cudaFuncAttributeMaxDynamicSharedMemorySize, GEMM_SMEM_BYTES);
    cudaFuncSetAttribute(k_gemm<HDIM, 2>, cudaFuncAttributeMaxDynamicSharedMemorySize, GEMM_SMEM_BYTES);

    // 1: x0 (+fp16) + counts + pack B
    k_build_count<<<(NN * IN1 + TPB - 1) / TPB, TPB>>>(x, ei, et, basis1, root1, basis2, root2);
    // 2: parallel scan
    k_scanA<<<NBP, 1024>>>();
    k_scanB<<<1, 1024>>>();
    k_scanC<<<NBP, 1024>>>();
    // 3: CSR fill + embeddings
    k_fill_embs<<<(FILL_TOT + TPB - 1) / TPB, TPB>>>(ei, et, gidx, pidx, gemb, pemb);
    // 4: aggregate layer 1
    k_agg<IN1, 1, 4><<<NN / 4, (IN1 / 4) * 4>>>(comp1);
    // 5: GEMM layer 1
    k_gemm<IN1, 1><<<(NN + 127) / 128, 256, GEMM_SMEM_BYTES>>>(bias1, att1, predw, predb, out);
    // 6: aggregate layer 2
    k_agg<HDIM, 2, 4><<<NN / 4, (HDIM / 4) * 4>>>(comp2);
    // 7: GEMM layer 2 + fused prediction head
    k_gemm<HDIM, 2><<<(NN + 127) / 128, 256, GEMM_SMEM_BYTES>>>(bias2, att2, predw, predb, out);
}